// round 1
// baseline (speedup 1.0000x reference)
#include <cuda_runtime.h>
#include <math.h>

// Problem constants
#define BTOT   1792          // N*D*H = 1*32*56
#define KW     56            // axial length
#define NCH    128           // 2*OUT_C
#define CH_STR 7168          // 128*56
#define XPLANE 100352        // 32*56*56 (per-channel plane of x) == B*KW
#define NQKV   100352.0      // BN count for qkv/out channels
#define NSIM   5619712.0     // BN count for sim channels (B*56*56)
#define EPSBN  1e-5f

// ---------------- scratch (device globals; no runtime alloc) ----------------
__device__ float g_qkv[BTOT * NCH * KW];   // [b][o][i]  o = g*16+cc (q:0-3,k:4-7,v:8-15)
__device__ float g_so [BTOT * NCH * KW];   // [b][o2][i] o2 = g*16 + c*2 + (sve?1:0)
__device__ double g_qsum[128], g_qsq[128];
__device__ double g_ssum[24],  g_ssq[24];
__device__ double g_osum[128], g_osq[128];
__device__ float g_qscale[128], g_qoff[128];
__device__ float g_simc[32];               // [0..7] c_qk  [8..15] c_qr(*0.1) [16..23] c_kr(*0.1) [24..31] offset
__device__ float g_oscale[128], g_ooff[128];

// ---------------- K0: zero stat accumulators (graph-replay safe) ------------
__global__ void k_zero() {
    int t = threadIdx.x;
    if (t < 128) { g_qsum[t] = 0.0; g_qsq[t] = 0.0; g_osum[t] = 0.0; g_osq[t] = 0.0; }
    if (t < 24)  { g_ssum[t] = 0.0; g_ssq[t] = 0.0; }
}

// ---------------- K1: qkv = w @ x  (+ per-channel stats) --------------------
__global__ void __launch_bounds__(256) k_qkv(const float* __restrict__ x,
                                             const float* __restrict__ w) {
    __shared__ float xs[64][57];
    __shared__ float ws[128][65];
    const int b = blockIdx.x;
    for (int t = threadIdx.x; t < 64 * 56; t += 256) {
        int c = t / 56, i = t % 56;
        xs[c][i] = x[c * XPLANE + b * 56 + i];
    }
    for (int t = threadIdx.x; t < 128 * 64; t += 256)
        ws[t >> 6][t & 63] = w[t];
    __syncthreads();

    const int og = threadIdx.x >> 3;        // 0..31  (4 output channels each)
    const int ig = threadIdx.x & 7;         // 0..7   (7 positions each)
    const int o0 = og * 4, i0 = ig * 7;
    float acc[4][7];
#pragma unroll
    for (int a = 0; a < 4; a++)
#pragma unroll
        for (int c2 = 0; c2 < 7; c2++) acc[a][c2] = 0.f;

    for (int c = 0; c < 64; ++c) {
        float w0 = ws[o0][c], w1 = ws[o0 + 1][c], w2 = ws[o0 + 2][c], w3 = ws[o0 + 3][c];
#pragma unroll
        for (int ii = 0; ii < 7; ++ii) {
            float xv = xs[c][i0 + ii];
            acc[0][ii] += w0 * xv; acc[1][ii] += w1 * xv;
            acc[2][ii] += w2 * xv; acc[3][ii] += w3 * xv;
        }
    }
    float* outb = g_qkv + (size_t)b * CH_STR;
#pragma unroll
    for (int oo = 0; oo < 4; ++oo) {
        float s = 0.f, sq = 0.f;
#pragma unroll
        for (int ii = 0; ii < 7; ++ii) {
            float v = acc[oo][ii];
            outb[(o0 + oo) * 56 + i0 + ii] = v;
            s += v; sq += v * v;
        }
        // reduce over the 8 ig-lanes (consecutive within warp)
        for (int off = 4; off; off >>= 1) {
            s  += __shfl_down_sync(0xffffffffu, s,  off);
            sq += __shfl_down_sync(0xffffffffu, sq, off);
        }
        if (ig == 0) {
            atomicAdd(&g_qsum[o0 + oo], (double)s);
            atomicAdd(&g_qsq [o0 + oo], (double)sq);
        }
    }
}

// ---------------- K2: finalize qkv BN ---------------------------------------
__global__ void k_fin_qkv(const float* __restrict__ gg, const float* __restrict__ bb) {
    int o = threadIdx.x;
    if (o < 128) {
        double inv = 1.0 / NQKV;
        double m = g_qsum[o] * inv;
        double v = g_qsq[o] * inv - m * m;
        float sc = gg[o] * rsqrtf((float)v + EPSBN);
        g_qscale[o] = sc;
        g_qoff[o]   = bb[o] - (float)m * sc;
    }
}

// ---------------- K3: similarity-channel stats (qk, qr*0.1, kr*0.1) ---------
__global__ void __launch_bounds__(224) k_simstats(const float* __restrict__ relative) {
    __shared__ float qs[8][4][56];
    __shared__ float ks[8][4][56];
    __shared__ float rel[8][112];
    __shared__ float wred[8][6];
    const int b = blockIdx.x;
    const int t = threadIdx.x;

    for (int idx = t; idx < 64 * 56; idx += 224) {
        int c8 = idx / 56, i = idx % 56;
        int g = c8 >> 3, cc = c8 & 7;
        int o = g * 16 + cc;
        float v = g_qkv[(size_t)b * CH_STR + o * 56 + i] * g_qscale[o] + g_qoff[o];
        if (cc < 4) qs[g][cc][i] = v; else ks[g][cc - 4][i] = v;
    }
    for (int idx = t; idx < 8 * 111; idx += 224)
        rel[idx / 111][idx % 111] = relative[idx];
    __syncthreads();

    const int i = t % 56, jg = t / 56;
    const int lane = t & 31, warp = t >> 5;

    for (int g = 0; g < 8; ++g) {
        float q0 = qs[g][0][i], q1 = qs[g][1][i], q2 = qs[g][2][i], q3 = qs[g][3][i];
        float c0 = ks[g][0][i], c1 = ks[g][1][i], c2 = ks[g][2][i], c3 = ks[g][3][i];
        float s0 = 0, s1 = 0, s2 = 0, t0 = 0, t1 = 0, t2 = 0;
#pragma unroll
        for (int jj = 0; jj < 14; ++jj) {
            int j = jg * 14 + jj;
            int dq = i - j + 55;
            float r0 = rel[0][dq], r1 = rel[1][dq], r2 = rel[2][dq], r3 = rel[3][dq];
            float r4 = rel[4][dq], r5 = rel[5][dq], r6 = rel[6][dq], r7 = rel[7][dq];
            float k0 = ks[g][0][j], k1 = ks[g][1][j], k2 = ks[g][2][j], k3 = ks[g][3][j];
            float qk = q0 * k0 + q1 * k1 + q2 * k2 + q3 * k3;
            float qr = (q0 * r0 + q1 * r1 + q2 * r2 + q3 * r3) * 0.1f;
            // kr stats are transpose-invariant: accumulate kr_pre[i,j] = sum_c k[c,i]*rel[4+c][i-j+55]
            float kr = (c0 * r4 + c1 * r5 + c2 * r6 + c3 * r7) * 0.1f;
            s0 += qk; t0 += qk * qk;
            s1 += qr; t1 += qr * qr;
            s2 += kr; t2 += kr * kr;
        }
        float vals[6] = {s0, s1, s2, t0, t1, t2};
#pragma unroll
        for (int v6 = 0; v6 < 6; ++v6) {
            float xv = vals[v6];
            for (int off = 16; off; off >>= 1) xv += __shfl_down_sync(0xffffffffu, xv, off);
            if (lane == 0) wred[warp][v6] = xv;
        }
        __syncthreads();
        if (t < 6) {
            float xv = 0;
            for (int wdx = 0; wdx < 7; ++wdx) xv += wred[wdx][t];
            if (t < 3) atomicAdd(&g_ssum[t * 8 + g], (double)xv);
            else       atomicAdd(&g_ssq[(t - 3) * 8 + g], (double)xv);
        }
        __syncthreads();
    }
}

// ---------------- K4: finalize sim BN → folded per-head coefficients --------
__global__ void k_fin_sim(const float* __restrict__ sg, const float* __restrict__ sb) {
    __shared__ float a[24], bp[24];
    int t = threadIdx.x;
    if (t < 24) {
        double inv = 1.0 / NSIM;
        double m = g_ssum[t] * inv;
        double v = g_ssq[t] * inv - m * m;
        float aa = sg[t] * rsqrtf((float)v + EPSBN);
        a[t] = aa;
        bp[t] = sb[t] - (float)m * aa;
    }
    __syncthreads();
    if (t < 8) {
        g_simc[t]      = a[t];               // applied to raw qk
        g_simc[8 + t]  = a[8 + t]  * 0.1f;   // applied to raw qr
        g_simc[16 + t] = a[16 + t] * 0.1f;   // applied to raw kr
        g_simc[24 + t] = bp[t] + bp[8 + t] + bp[16 + t];
    }
}

// ---------------- K5: attention (logits -> softmax -> sv/sve) + out stats ---
__global__ void __launch_bounds__(224) k_attn(const float* __restrict__ relative) {
    __shared__ __align__(16) float qs[4][56];
    __shared__ __align__(16) float ks[4][56];
    __shared__ __align__(16) float vs[8][56];
    __shared__ float rel[8][112];
    __shared__ __align__(16) float relvT[111][8];
    __shared__ __align__(16) float P[56][60];
    __shared__ float red[4][56];
    __shared__ float rinv[56];
    __shared__ float SB[16][57];

    const int b = blockIdx.x >> 3, g = blockIdx.x & 7;
    const int t = threadIdx.x;

    for (int idx = t; idx < 16 * 56; idx += 224) {
        int cc = idx / 56, i = idx % 56;
        int o = g * 16 + cc;
        float v = g_qkv[(size_t)b * CH_STR + o * 56 + i] * g_qscale[o] + g_qoff[o];
        if (cc < 4) qs[cc][i] = v;
        else if (cc < 8) ks[cc - 4][i] = v;
        else vs[cc - 8][i] = v;
    }
    for (int idx = t; idx < 16 * 111; idx += 224) {
        int r = idx / 111, d = idx % 111;
        float v = relative[idx];
        if (r < 8) rel[r][d] = v; else relvT[d][r - 8] = v;
    }
    __syncthreads();

    const float cqk = g_simc[g], cqr = g_simc[8 + g], ckr = g_simc[16 + g], soff = g_simc[24 + g];

    // ---- logits + softmax (unnormalized probs; deferred 1/rowsum) ----
    {
        const int i = t % 56, jg = t / 56;
        float q0 = qs[0][i], q1 = qs[1][i], q2 = qs[2][i], q3 = qs[3][i];
        float lmax = -1e30f;
#pragma unroll
        for (int jj = 0; jj < 14; ++jj) {
            int j = jg * 14 + jj;
            int dq = i - j + 55, dk = 110 - dq;
            float k0 = ks[0][j], k1 = ks[1][j], k2 = ks[2][j], k3 = ks[3][j];
            float qk = q0 * k0 + q1 * k1 + q2 * k2 + q3 * k3;
            float qr = q0 * rel[0][dq] + q1 * rel[1][dq] + q2 * rel[2][dq] + q3 * rel[3][dq];
            float kr = k0 * rel[4][dk] + k1 * rel[5][dk] + k2 * rel[6][dk] + k3 * rel[7][dk];
            float l = cqk * qk + cqr * qr + ckr * kr + soff;
            P[i][j] = l;
            lmax = fmaxf(lmax, l);
        }
        red[jg][i] = lmax;
        __syncthreads();
        float rm = fmaxf(fmaxf(red[0][i], red[1][i]), fmaxf(red[2][i], red[3][i]));
        __syncthreads();                    // protect red before reuse
        float ls = 0.f;
#pragma unroll
        for (int jj = 0; jj < 14; ++jj) {
            int j = jg * 14 + jj;
            float p = __expf(P[i][j] - rm);
            P[i][j] = p;
            ls += p;
        }
        red[jg][i] = ls;
        __syncthreads();
        if (t < 56) rinv[t] = 1.0f / (red[0][t] + red[1][t] + red[2][t] + red[3][t]);
        __syncthreads();
    }

    // ---- sv / sve ----
    {
        const int c2 = t & 3, i = t >> 2;   // i in [0,56)
        const int c = c2 * 2;
        float aS0 = 0, aS1 = 0, aE0 = 0, aE1 = 0;
        const float4* pr = (const float4*)&P[i][0];
        const float4* va = (const float4*)&vs[c][0];
        const float4* vb = (const float4*)&vs[c + 1][0];
#pragma unroll
        for (int j4 = 0; j4 < 14; ++j4) {
            float4 p = pr[j4];
            float4 a4 = va[j4], b4 = vb[j4];
            aS0 += p.x * a4.x + p.y * a4.y + p.z * a4.z + p.w * a4.w;
            aS1 += p.x * b4.x + p.y * b4.y + p.z * b4.z + p.w * b4.w;
            int d = i - j4 * 4 + 55;
            float2 r0 = *(const float2*)&relvT[d][c];
            float2 r1 = *(const float2*)&relvT[d - 1][c];
            float2 r2 = *(const float2*)&relvT[d - 2][c];
            float2 r3 = *(const float2*)&relvT[d - 3][c];
            aE0 += p.x * r0.x + p.y * r1.x + p.z * r2.x + p.w * r3.x;
            aE1 += p.x * r0.y + p.y * r1.y + p.z * r2.y + p.w * r3.y;
        }
        float inv = rinv[i];
        SB[c * 2][i]     = aS0 * inv;            // F_SV = 1.0
        SB[c * 2 + 1][i] = aE0 * inv * 0.1f;     // F_SVE
        SB[c * 2 + 2][i] = aS1 * inv;
        SB[c * 2 + 3][i] = aE1 * inv * 0.1f;
    }
    __syncthreads();

    // ---- coalesced write to g_so + per-channel stats ----
    float* ob = g_so + (size_t)b * CH_STR + g * 16 * 56;
    for (int idx = t; idx < 16 * 56; idx += 224)
        ob[idx] = SB[idx / 56][idx % 56];
    if (t < 32) {
        int row = t >> 1, which = t & 1;
        float s = 0.f;
        for (int i2 = 0; i2 < 56; ++i2) {
            float v = SB[row][i2];
            s += which ? v * v : v;
        }
        if (which) atomicAdd(&g_osq [g * 16 + row], (double)s);
        else       atomicAdd(&g_osum[g * 16 + row], (double)s);
    }
}

// ---------------- K6: finalize out BN ---------------------------------------
__global__ void k_fin_out(const float* __restrict__ gg, const float* __restrict__ bb) {
    int o = threadIdx.x;
    if (o < 128) {
        double inv = 1.0 / NQKV;
        double m = g_osum[o] * inv;
        double v = g_osq[o] * inv - m * m;
        float sc = gg[o] * rsqrtf((float)v + EPSBN);
        g_oscale[o] = sc;
        g_ooff[o]   = bb[o] - (float)m * sc;
    }
}

// ---------------- K7: apply out BN + pair-sum + final layout ----------------
__global__ void __launch_bounds__(256) k_out(float* __restrict__ out) {
    int idx = blockIdx.x * 256 + threadIdx.x;   // float4 index
    if (idx >= 1605632) return;                 // 6422528/4
    int e  = idx * 4;
    int cp = e / XPLANE;                        // output channel 0..63
    int r  = e % XPLANE;
    int bq = r / 56, i = r % 56;
    const float* base = g_so + (size_t)bq * CH_STR + (2 * cp) * 56 + i;
    float4 s0 = *(const float4*)base;
    float4 s1 = *(const float4*)(base + 56);
    float sc0 = g_oscale[2 * cp], of0 = g_ooff[2 * cp];
    float sc1 = g_oscale[2 * cp + 1], of1 = g_ooff[2 * cp + 1];
    float4 o4;
    o4.x = s0.x * sc0 + of0 + s1.x * sc1 + of1;
    o4.y = s0.y * sc0 + of0 + s1.y * sc1 + of1;
    o4.z = s0.z * sc0 + of0 + s1.z * sc1 + of1;
    o4.w = s0.w * sc0 + of0 + s1.w * sc1 + of1;
    *(float4*)&out[e] = o4;
}

// ---------------- launch -----------------------------------------------------
extern "C" void kernel_launch(void* const* d_in, const int* in_sizes, int n_in,
                              void* d_out, int out_size) {
    const float* x        = (const float*)d_in[0];
    const float* w_qkv    = (const float*)d_in[1];
    const float* relative = (const float*)d_in[2];
    const float* qg       = (const float*)d_in[3];
    const float* qb       = (const float*)d_in[4];
    const float* sg       = (const float*)d_in[5];
    const float* sb       = (const float*)d_in[6];
    const float* og       = (const float*)d_in[7];
    const float* ob       = (const float*)d_in[8];
    float* out            = (float*)d_out;

    k_zero    <<<1, 128>>>();
    k_qkv     <<<BTOT, 256>>>(x, w_qkv);
    k_fin_qkv <<<1, 128>>>(qg, qb);
    k_simstats<<<BTOT, 224>>>(relative);
    k_fin_sim <<<1, 32>>>(sg, sb);
    k_attn    <<<BTOT * 8, 224>>>(relative);
    k_fin_out <<<1, 128>>>(og, ob);
    k_out     <<<6272, 256>>>(out);
}

// round 2
// speedup vs baseline: 1.3315x; 1.3315x over previous
#include <cuda_runtime.h>
#include <math.h>

// Problem constants
#define BTOT   1792          // N*D*H = 1*32*56
#define CH_STR 7168          // 128*56
#define XPLANE 100352        // 32*56*56 == BTOT*56
#define NQKV   100352.0
#define NSIM   5619712.0     // BTOT*56*56
#define EPSBN  1e-5f

// ---------------- scratch (device globals; no runtime alloc) ----------------
__device__ float g_qkv[BTOT * 128 * 56];   // [b][o][i]  o = g*16+cc (q:0-3,k:4-7,v:8-15)
__device__ float g_so [BTOT * 128 * 56];   // [b][o2][i] o2 = g*16 + c*2 + (sve?1:0)
__device__ double g_qsum[128], g_qsq[128];
__device__ double g_ssum[24],  g_ssq[24];
__device__ double g_osum[128], g_osq[128];
__device__ float g_qscale[128], g_qoff[128];
__device__ float g_simc[32];               // folded sim-BN coefficients per head
__device__ float g_oscale[128], g_ooff[128];
// precomputed relative-embedding moment tables
__device__ float g_SR[8][56];              // SR_c(i)   = sum_{d=i}^{i+55} rel[c][d]
__device__ float g_TQ[10][56];             // w_p * sum rel[a]rel[b] (q channels 0-3)
__device__ float g_TK[10][56];             // w_p * sum rel[a]rel[b] (k channels 4-7)

__constant__ int   c_PA[10] = {0,0,0,0,1,1,1,2,2,3};
__constant__ int   c_PB[10] = {0,1,2,3,1,2,3,2,3,3};
__constant__ float c_PW[10] = {1.f,2.f,2.f,2.f,1.f,2.f,2.f,1.f,2.f,1.f};

// ---------------- K0: zero stat accumulators (graph-replay safe) ------------
__global__ void k_zero() {
    int t = threadIdx.x;
    if (t < 128) { g_qsum[t] = 0.0; g_qsq[t] = 0.0; g_osum[t] = 0.0; g_osq[t] = 0.0; }
    if (t < 24)  { g_ssum[t] = 0.0; g_ssq[t] = 0.0; }
}

// ---------------- K_prep: prefix tables of relative -------------------------
__global__ void k_prep(const float* __restrict__ relative) {
    __shared__ float rel[8][112];
    int t = threadIdx.x;
    for (int idx = t; idx < 8 * 111; idx += 256)
        rel[idx / 111][idx % 111] = relative[idx];
    __syncthreads();
    for (int task = t; task < 448; task += 256) {
        int c = task / 56, i = task % 56;
        float s = 0.f;
        for (int d = 0; d < 56; ++d) s += rel[c][i + d];
        g_SR[c][i] = s;
    }
    for (int task = t; task < 1120; task += 256) {
        int p = task / 56, i = task % 56;
        int pp = p % 10; int isK = (p >= 10) ? 4 : 0;
        int a = c_PA[pp] + isK, bb = c_PB[pp] + isK;
        float s = 0.f;
        for (int d = 0; d < 56; ++d) s += rel[a][i + d] * rel[bb][i + d];
        s *= c_PW[pp];
        if (isK) g_TK[pp][i] = s; else g_TQ[pp][i] = s;
    }
}

// ---------------- K1: qkv = w @ x  (+ per-channel stats) --------------------
__global__ void __launch_bounds__(256) k_qkv(const float* __restrict__ x,
                                             const float* __restrict__ w) {
    __shared__ float xs[64][57];
    __shared__ float ws[128][65];
    const int b = blockIdx.x;
    for (int t = threadIdx.x; t < 64 * 56; t += 256) {
        int c = t / 56, i = t % 56;
        xs[c][i] = x[c * XPLANE + b * 56 + i];
    }
    for (int t = threadIdx.x; t < 128 * 64; t += 256)
        ws[t >> 6][t & 63] = w[t];
    __syncthreads();

    const int og = threadIdx.x >> 3;
    const int ig = threadIdx.x & 7;
    const int o0 = og * 4, i0 = ig * 7;
    float acc[4][7];
#pragma unroll
    for (int a = 0; a < 4; a++)
#pragma unroll
        for (int c2 = 0; c2 < 7; c2++) acc[a][c2] = 0.f;

    for (int c = 0; c < 64; ++c) {
        float w0 = ws[o0][c], w1 = ws[o0 + 1][c], w2 = ws[o0 + 2][c], w3 = ws[o0 + 3][c];
#pragma unroll
        for (int ii = 0; ii < 7; ++ii) {
            float xv = xs[c][i0 + ii];
            acc[0][ii] += w0 * xv; acc[1][ii] += w1 * xv;
            acc[2][ii] += w2 * xv; acc[3][ii] += w3 * xv;
        }
    }
    float* outb = g_qkv + (size_t)b * CH_STR;
#pragma unroll
    for (int oo = 0; oo < 4; ++oo) {
        float s = 0.f, sq = 0.f;
#pragma unroll
        for (int ii = 0; ii < 7; ++ii) {
            float v = acc[oo][ii];
            outb[(o0 + oo) * 56 + i0 + ii] = v;
            s += v; sq += v * v;
        }
        for (int off = 4; off; off >>= 1) {
            s  += __shfl_down_sync(0xffffffffu, s,  off);
            sq += __shfl_down_sync(0xffffffffu, sq, off);
        }
        if (ig == 0) {
            atomicAdd(&g_qsum[o0 + oo], (double)s);
            atomicAdd(&g_qsq [o0 + oo], (double)sq);
        }
    }
}

// ---------------- K2: finalize qkv BN ---------------------------------------
__global__ void k_fin_qkv(const float* __restrict__ gg, const float* __restrict__ bb) {
    int o = threadIdx.x;
    if (o < 128) {
        double inv = 1.0 / NQKV;
        double m = g_qsum[o] * inv;
        double v = g_qsq[o] * inv - m * m;
        float sc = gg[o] * rsqrtf((float)v + EPSBN);
        g_qscale[o] = sc;
        g_qoff[o]   = bb[o] - (float)m * sc;
    }
}

// ---------------- K3: analytic sim moments (replaces O(K^2) stats pass) -----
// sum_ij qk   = sum_c (sum_i q_ci)(sum_j k_cj)
// sum_ij qk^2 = sum_cc' Gq[cc'] Gk[cc']
// sum_ij qr   = sum_{c,i} q_ci SR_c(i);  sum_ij qr^2 = sum_i sum_cc' q_ci q_c'i TQ_cc'(i)
// kr identical with k / SR[4..7] / TK (stats are transpose-invariant).
__global__ void __launch_bounds__(256) k_mom() {
    const int b = blockIdx.x;
    const int g = threadIdx.x >> 5;
    const int lane = threadIdx.x & 31;
    const float* base = g_qkv + (size_t)b * CH_STR + g * 16 * 56;

    float part[32];
#pragma unroll
    for (int v = 0; v < 32; ++v) part[v] = 0.f;
    // part layout: [0..3] sq_c  [4..7] sk_c  [8..17] Gq_p  [18..27] Gk_p
    //              [28] s1qr [29] s2qr [30] s1kr [31] s2kr

#pragma unroll
    for (int ii = 0; ii < 2; ++ii) {
        int i = lane + ii * 32;
        if (i < 56) {
            float q[4], k[4];
#pragma unroll
            for (int c = 0; c < 4; ++c) {
                int oq = g * 16 + c, ok = g * 16 + 4 + c;
                q[c] = base[c * 56 + i]       * g_qscale[oq] + g_qoff[oq];
                k[c] = base[(4 + c) * 56 + i] * g_qscale[ok] + g_qoff[ok];
            }
#pragma unroll
            for (int c = 0; c < 4; ++c) {
                part[c]     += q[c];
                part[4 + c] += k[c];
                part[28] += q[c] * g_SR[c][i];
                part[30] += k[c] * g_SR[4 + c][i];
            }
#pragma unroll
            for (int p = 0; p < 10; ++p) {
                float pq = q[c_PA[p]] * q[c_PB[p]];
                float pk = k[c_PA[p]] * k[c_PB[p]];
                part[8 + p]  += pq;
                part[18 + p] += pk;
                part[29] += pq * g_TQ[p][i];   // TQ prescaled by pair weight
                part[31] += pk * g_TK[p][i];
            }
        }
    }
#pragma unroll
    for (int v = 0; v < 32; ++v)
        for (int off = 16; off; off >>= 1)
            part[v] += __shfl_down_sync(0xffffffffu, part[v], off);

    if (lane == 0) {
        float S1 = 0.f, S2 = 0.f;
#pragma unroll
        for (int c = 0; c < 4; ++c) S1 += part[c] * part[4 + c];
#pragma unroll
        for (int p = 0; p < 10; ++p) S2 += c_PW[p] * part[8 + p] * part[18 + p];
        atomicAdd(&g_ssum[g],      (double)S1);
        atomicAdd(&g_ssq [g],      (double)S2);
        atomicAdd(&g_ssum[8 + g],  (double)(0.1f  * part[28]));
        atomicAdd(&g_ssq [8 + g],  (double)(0.01f * part[29]));
        atomicAdd(&g_ssum[16 + g], (double)(0.1f  * part[30]));
        atomicAdd(&g_ssq [16 + g], (double)(0.01f * part[31]));
    }
}

// ---------------- K4: finalize sim BN → folded per-head coefficients --------
__global__ void k_fin_sim(const float* __restrict__ sg, const float* __restrict__ sb) {
    __shared__ float a[24], bp[24];
    int t = threadIdx.x;
    if (t < 24) {
        double inv = 1.0 / NSIM;
        double m = g_ssum[t] * inv;
        double v = g_ssq[t] * inv - m * m;
        float aa = sg[t] * rsqrtf((float)v + EPSBN);
        a[t] = aa;
        bp[t] = sb[t] - (float)m * aa;
    }
    __syncthreads();
    if (t < 8) {
        g_simc[t]      = a[t];
        g_simc[8 + t]  = a[8 + t]  * 0.1f;
        g_simc[16 + t] = a[16 + t] * 0.1f;
        g_simc[24 + t] = bp[t] + bp[8 + t] + bp[16 + t];
    }
}

// ---------------- K5: attention — register-resident P, float4 tables --------
__global__ void __launch_bounds__(224, 4) k_attn(const float* __restrict__ relative) {
    __shared__ __align__(16) float qs[4][56];
    __shared__ __align__(16) float ksT[56][4];
    __shared__ __align__(16) float vsT[56][8];
    __shared__ __align__(16) float relqT[111][4];
    __shared__ __align__(16) float relkT[111][4];
    __shared__ __align__(16) float relvT[111][12];   // pad 12 -> conflict-free stride
    __shared__ float red[4][56];
    __shared__ float rinv[56];
    __shared__ float pacc[4 * 56 * 17];              // [jg][i][c16], stride 17
    __shared__ float SB[16][57];

    const int b = blockIdx.x >> 3, g = blockIdx.x & 7;
    const int t = threadIdx.x;

    for (int idx = t; idx < 16 * 56; idx += 224) {
        int cc = idx / 56, i = idx % 56;
        int o = g * 16 + cc;
        float v = g_qkv[(size_t)b * CH_STR + o * 56 + i] * g_qscale[o] + g_qoff[o];
        if (cc < 4) qs[cc][i] = v;
        else if (cc < 8) ksT[i][cc - 4] = v;
        else vsT[i][cc - 8] = v;
    }
    for (int idx = t; idx < 16 * 111; idx += 224) {
        int c = idx / 111, d = idx % 111;
        float v = relative[idx];
        if (c < 4) relqT[d][c] = v;
        else if (c < 8) relkT[d][c - 4] = v;
        else relvT[d][c - 8] = v;
    }
    __syncthreads();

    const float cqk = g_simc[g], cqr = g_simc[8 + g], ckr = g_simc[16 + g], soff = g_simc[24 + g];
    const int i = t % 56, jg = t / 56;
    const int jbase = jg * 14;

    // ---- phase 1: logits into registers ----
    float P[14];
    float lmax = -1e30f;
    {
        float q0 = qs[0][i], q1 = qs[1][i], q2 = qs[2][i], q3 = qs[3][i];
#pragma unroll
        for (int jj = 0; jj < 14; ++jj) {
            int j = jbase + jj;
            int dq = i - j + 55;
            float4 kv = *(const float4*)ksT[j];
            float4 rq = *(const float4*)relqT[dq];
            float4 rk = *(const float4*)relkT[110 - dq];
            float qk = q0 * kv.x + q1 * kv.y + q2 * kv.z + q3 * kv.w;
            float qr = q0 * rq.x + q1 * rq.y + q2 * rq.z + q3 * rq.w;
            float kr = kv.x * rk.x + kv.y * rk.y + kv.z * rk.z + kv.w * rk.w;
            float l = fmaf(cqk, qk, fmaf(cqr, qr, fmaf(ckr, kr, soff)));
            P[jj] = l;
            lmax = fmaxf(lmax, l);
        }
    }

    // ---- phase 2: softmax (unnormalized, deferred 1/rowsum) ----
    red[jg][i] = lmax;
    __syncthreads();
    float rm = fmaxf(fmaxf(red[0][i], red[1][i]), fmaxf(red[2][i], red[3][i]));
    __syncthreads();
    float ls = 0.f;
#pragma unroll
    for (int jj = 0; jj < 14; ++jj) {
        float p = __expf(P[jj] - rm);
        P[jj] = p;
        ls += p;
    }
    red[jg][i] = ls;
    __syncthreads();
    if (t < 56) rinv[t] = 1.0f / (red[0][t] + red[1][t] + red[2][t] + red[3][t]);

    // ---- phase 3: sv/sve partials (P in registers) ----
    float acc[16];
#pragma unroll
    for (int c = 0; c < 16; ++c) acc[c] = 0.f;
#pragma unroll
    for (int jj = 0; jj < 14; ++jj) {
        int j = jbase + jj;
        float p = P[jj];
        int d = i - j + 55;
        float4 va = *(const float4*)&vsT[j][0];
        float4 vb = *(const float4*)&vsT[j][4];
        float4 ra = *(const float4*)&relvT[d][0];
        float4 rb = *(const float4*)&relvT[d][4];
        acc[0] += p * va.x; acc[1] += p * va.y; acc[2] += p * va.z; acc[3] += p * va.w;
        acc[4] += p * vb.x; acc[5] += p * vb.y; acc[6] += p * vb.z; acc[7] += p * vb.w;
        acc[8]  += p * ra.x; acc[9]  += p * ra.y; acc[10] += p * ra.z; acc[11] += p * ra.w;
        acc[12] += p * rb.x; acc[13] += p * rb.y; acc[14] += p * rb.z; acc[15] += p * rb.w;
    }
    {
        float* pr = &pacc[(jg * 56 + i) * 17];
#pragma unroll
        for (int c = 0; c < 16; ++c) pr[c] = acc[c];
    }
    __syncthreads();

    // ---- combine partials over jg, scale, stage to SB ----
#pragma unroll
    for (int r = 0; r < 4; ++r) {
        int idx = t + r * 224;                 // 0..895
        int c16 = idx / 56, i2 = idx % 56;
        float s = pacc[(0 * 56 + i2) * 17 + c16] + pacc[(1 * 56 + i2) * 17 + c16]
                + pacc[(2 * 56 + i2) * 17 + c16] + pacc[(3 * 56 + i2) * 17 + c16];
        float val = s * rinv[i2] * (c16 < 8 ? 1.0f : 0.1f);
        int row = (c16 < 8) ? (2 * c16) : (2 * (c16 - 8) + 1);
        SB[row][i2] = val;
    }
    __syncthreads();

    // ---- coalesced write to g_so + per-channel out stats ----
    float* ob = g_so + (size_t)b * CH_STR + g * 16 * 56;
    for (int idx = t; idx < 16 * 56; idx += 224)
        ob[idx] = SB[idx / 56][idx % 56];
    if (t < 32) {
        int row = t >> 1, which = t & 1;
        float s = 0.f;
        for (int i2 = 0; i2 < 56; ++i2) {
            float v = SB[row][i2];
            s += which ? v * v : v;
        }
        if (which) atomicAdd(&g_osq [g * 16 + row], (double)s);
        else       atomicAdd(&g_osum[g * 16 + row], (double)s);
    }
}

// ---------------- K6: finalize out BN ---------------------------------------
__global__ void k_fin_out(const float* __restrict__ gg, const float* __restrict__ bb) {
    int o = threadIdx.x;
    if (o < 128) {
        double inv = 1.0 / NQKV;
        double m = g_osum[o] * inv;
        double v = g_osq[o] * inv - m * m;
        float sc = gg[o] * rsqrtf((float)v + EPSBN);
        g_oscale[o] = sc;
        g_ooff[o]   = bb[o] - (float)m * sc;
    }
}

// ---------------- K7: apply out BN + pair-sum + final layout ----------------
__global__ void __launch_bounds__(256) k_out(float* __restrict__ out) {
    int idx = blockIdx.x * 256 + threadIdx.x;
    if (idx >= 1605632) return;
    int e  = idx * 4;
    int cp = e / XPLANE;
    int r  = e % XPLANE;
    int bq = r / 56, i = r % 56;
    const float* base = g_so + (size_t)bq * CH_STR + (2 * cp) * 56 + i;
    float4 s0 = *(const float4*)base;
    float4 s1 = *(const float4*)(base + 56);
    float sc0 = g_oscale[2 * cp], of0 = g_ooff[2 * cp];
    float sc1 = g_oscale[2 * cp + 1], of1 = g_ooff[2 * cp + 1];
    float4 o4;
    o4.x = s0.x * sc0 + of0 + s1.x * sc1 + of1;
    o4.y = s0.y * sc0 + of0 + s1.y * sc1 + of1;
    o4.z = s0.z * sc0 + of0 + s1.z * sc1 + of1;
    o4.w = s0.w * sc0 + of0 + s1.w * sc1 + of1;
    *(float4*)&out[e] = o4;
}

// ---------------- launch -----------------------------------------------------
extern "C" void kernel_launch(void* const* d_in, const int* in_sizes, int n_in,
                              void* d_out, int out_size) {
    const float* x        = (const float*)d_in[0];
    const float* w_qkv    = (const float*)d_in[1];
    const float* relative = (const float*)d_in[2];
    const float* qg       = (const float*)d_in[3];
    const float* qb       = (const float*)d_in[4];
    const float* sg       = (const float*)d_in[5];
    const float* sb       = (const float*)d_in[6];
    const float* og       = (const float*)d_in[7];
    const float* ob       = (const float*)d_in[8];
    float* out            = (float*)d_out;

    k_zero    <<<1, 128>>>();
    k_prep    <<<1, 256>>>(relative);
    k_qkv     <<<BTOT, 256>>>(x, w_qkv);
    k_fin_qkv <<<1, 128>>>(qg, qb);
    k_mom     <<<BTOT, 256>>>();
    k_fin_sim <<<1, 32>>>(sg, sb);
    k_attn    <<<BTOT * 8, 224>>>(relative);
    k_fin_out <<<1, 128>>>(og, ob);
    k_out     <<<6272, 256>>>(out);
}